// round 7
// baseline (speedup 1.0000x reference)
#include <cuda_runtime.h>
#include <cuda_bf16.h>
#include <cstdint>

#define BB    64
#define NNODE 1024
#define IND   512
#define HIDD  1024
#define LATD  256
#define TOK   (BB * NNODE)   // 65536

// ---------------------------------------------------------------------------
// Scratch (device globals — allocation is forbidden)
// ---------------------------------------------------------------------------
__device__ float g_d[TOK];
__device__ __align__(16) __nv_bfloat16 g_ahi[(size_t)BB * NNODE * NNODE];
__device__ __align__(16) __nv_bfloat16 g_alo[(size_t)BB * NNODE * NNODE];
__device__ __align__(16) __nv_bfloat16 g_xthi[(size_t)BB * IND * NNODE];
__device__ __align__(16) __nv_bfloat16 g_xtlo[(size_t)BB * IND * NNODE];
__device__ __align__(16) __nv_bfloat16 g_hhi[(size_t)TOK * IND];
__device__ __align__(16) __nv_bfloat16 g_hlo[(size_t)TOK * IND];
__device__ __align__(16) __nv_bfloat16 g_h1hi[(size_t)TOK * HIDD];
__device__ __align__(16) __nv_bfloat16 g_h1lo[(size_t)TOK * HIDD];
__device__ __align__(16) __nv_bfloat16 g_w1hi[HIDD * IND],  g_w1lo[HIDD * IND];
__device__ __align__(16) __nv_bfloat16 g_wcathi[2 * LATD * HIDD];   // [Wmu; Wlv]
__device__ __align__(16) __nv_bfloat16 g_wcatlo[2 * LATD * HIDD];

// ---------------------------------------------------------------------------
// helpers (baseline PTX only)
// ---------------------------------------------------------------------------
__device__ __forceinline__ uint32_t smem_u32(const void* p) {
    uint32_t a;
    asm("{ .reg .u64 t; cvta.to.shared.u64 t, %1; cvt.u32.u64 %0, t; }" : "=r"(a) : "l"(p));
    return a;
}
__device__ __forceinline__ void ldsm4(uint32_t addr, uint32_t* r) {
    asm volatile("ldmatrix.sync.aligned.m8n8.x4.shared.b16 {%0,%1,%2,%3}, [%4];"
                 : "=r"(r[0]), "=r"(r[1]), "=r"(r[2]), "=r"(r[3]) : "r"(addr));
}
__device__ __forceinline__ void mma16816(float* c, const uint32_t* a, const uint32_t* b) {
    asm volatile(
        "mma.sync.aligned.m16n8k16.row.col.f32.bf16.bf16.f32 "
        "{%0,%1,%2,%3}, {%4,%5,%6,%7}, {%8,%9}, {%0,%1,%2,%3};"
        : "+f"(c[0]), "+f"(c[1]), "+f"(c[2]), "+f"(c[3])
        : "r"(a[0]), "r"(a[1]), "r"(a[2]), "r"(a[3]), "r"(b[0]), "r"(b[1]));
}
__device__ __forceinline__ void cpasync16(uint32_t dst, const void* src) {
    asm volatile("cp.async.cg.shared.global [%0], [%1], 16;" :: "r"(dst), "l"(src) : "memory");
}
#define CP_COMMIT() asm volatile("cp.async.commit_group;" ::: "memory")
#define CP_WAIT0()  asm volatile("cp.async.wait_group 0;" ::: "memory")

// ---------------------------------------------------------------------------
// Fused: a -> (hi, lo) split AND degree d = rsqrt(rowsum + 1 + 1e-8)
// ---------------------------------------------------------------------------
__global__ void __launch_bounds__(256) dsplit_a_kernel(const float* __restrict__ a) {
    int warp = (blockIdx.x * 256 + threadIdx.x) >> 5;
    int lane = threadIdx.x & 31;
    const float4* row = (const float4*)(a + (size_t)warp * NNODE);
    __nv_bfloat162* hi = (__nv_bfloat162*)(g_ahi + (size_t)warp * NNODE);
    __nv_bfloat162* lo = (__nv_bfloat162*)(g_alo + (size_t)warp * NNODE);
    float s = 0.f;
#pragma unroll
    for (int j = 0; j < 8; j++) {
        int i4 = lane + j * 32;
        float4 v = row[i4];
        s += v.x + v.y + v.z + v.w;
        float f[4] = {v.x, v.y, v.z, v.w};
        __nv_bfloat16 h[4], l[4];
#pragma unroll
        for (int k = 0; k < 4; k++) {
            h[k] = __float2bfloat16(f[k]);
            l[k] = __float2bfloat16(f[k] - __bfloat162float(h[k]));
        }
        hi[2 * i4]     = __nv_bfloat162(h[0], h[1]);
        hi[2 * i4 + 1] = __nv_bfloat162(h[2], h[3]);
        lo[2 * i4]     = __nv_bfloat162(l[0], l[1]);
        lo[2 * i4 + 1] = __nv_bfloat162(l[2], l[3]);
    }
#pragma unroll
    for (int off = 16; off; off >>= 1) s += __shfl_xor_sync(0xffffffffu, s, off);
    if (lane == 0) g_d[warp] = rsqrtf(s + 1.0f + 1e-8f);
}

// ---------------------------------------------------------------------------
// Kernel: xt[b,c,j] = d[b,j] * x[b,j,c]  transposed + split into hi/lo
// ---------------------------------------------------------------------------
__global__ void __launch_bounds__(256) split_xt_kernel(const float* __restrict__ x) {
    __shared__ float t[32][33];
    int b  = blockIdx.z;
    int j0 = blockIdx.y * 32;
    int c0 = blockIdx.x * 32;
    int tx = threadIdx.x, ty = threadIdx.y;      // (32, 8)
#pragma unroll
    for (int k = 0; k < 4; k++) {
        int j = j0 + ty + k * 8;
        float dv = g_d[b * NNODE + j];
        t[ty + k * 8][tx] = x[((size_t)(b * NNODE + j)) * IND + c0 + tx] * dv;
    }
    __syncthreads();
#pragma unroll
    for (int k = 0; k < 4; k++) {
        int c = c0 + ty + k * 8;
        int j = j0 + tx;
        float v = t[tx][ty + k * 8];
        __nv_bfloat16 h = __float2bfloat16(v);
        size_t o = ((size_t)b * IND + c) * NNODE + j;
        g_xthi[o] = h;
        g_xtlo[o] = __float2bfloat16(v - __bfloat162float(h));
    }
}

// ---------------------------------------------------------------------------
// All weight splits in one kernel
// ---------------------------------------------------------------------------
#define W1_F4   (HIDD * IND / 4)          // 131072
#define WHD_F4  (LATD * HIDD / 4)         // 65536
__global__ void __launch_bounds__(256) split_w_kernel(const float* __restrict__ W1,
                                                      const float* __restrict__ Wmu,
                                                      const float* __restrict__ Wlv) {
    size_t i = (size_t)blockIdx.x * 256 + threadIdx.x;
    const float* src; __nv_bfloat16 *hi, *lo; size_t o;
    if (i < W1_F4)                 { src = W1;  hi = g_w1hi;  lo = g_w1lo;  o = i; }
    else if (i < W1_F4 + WHD_F4)   { src = Wmu; hi = g_wcathi; lo = g_wcatlo; o = i - W1_F4; }
    else                           { src = Wlv; hi = g_wcathi + (size_t)LATD * HIDD;
                                     lo = g_wcatlo + (size_t)LATD * HIDD; o = i - W1_F4 - WHD_F4; }
    float4 v = ((const float4*)src)[o];
    float f[4] = {v.x, v.y, v.z, v.w};
    __nv_bfloat16 h[4], l[4];
#pragma unroll
    for (int k = 0; k < 4; k++) {
        h[k] = __float2bfloat16(f[k]);
        l[k] = __float2bfloat16(f[k] - __bfloat162float(h[k]));
    }
    ((__nv_bfloat162*)hi)[2 * o]     = __nv_bfloat162(h[0], h[1]);
    ((__nv_bfloat162*)hi)[2 * o + 1] = __nv_bfloat162(h[2], h[3]);
    ((__nv_bfloat162*)lo)[2 * o]     = __nv_bfloat162(l[0], l[1]);
    ((__nv_bfloat162*)lo)[2 * o + 1] = __nv_bfloat162(l[2], l[3]);
}

// ---------------------------------------------------------------------------
// Split-bf16 GEMM via mma.sync (HMMA): D[m,n] = sum_k A[m,k]*B[n,k]
// CTA tile 128x64, warp tile 32x32, KC=32, 3 CTAs/SM target (occupancy fix).
//   3-term compensation: Ahi*Bhi + Ahi*Blo + Alo*Bhi  (fp32-equivalent)
// SMEM per buffer: Ahi@0 (10240) Alo@10240 Bhi@20480 (5120) Blo@25600 -> 30720
// EPI: 0 = message passing (hi/lo out), 1 = bias+relu (hi/lo out),
//      3 = dual-head bias (cols<256 -> mu else logvar), fp32 out
// ---------------------------------------------------------------------------
#define BUF_B  30720
#define GEMM_SMEM 61440
#define STG_STRIDE 144      // (64+8) bf16 per row

template <int KDIM, int EPI, int LDO>
__global__ void __launch_bounds__(256, 3) gemm_k(
    const __nv_bfloat16* __restrict__ Ahi, const __nv_bfloat16* __restrict__ Alo,
    const __nv_bfloat16* __restrict__ Bhi, const __nv_bfloat16* __restrict__ Blo,
    long bstride,
    float* __restrict__ outf,
    __nv_bfloat16* __restrict__ ohi, __nv_bfloat16* __restrict__ olo,
    const float* __restrict__ bias, const float* __restrict__ bias2,
    const float* __restrict__ xdiag)
{
    extern __shared__ char smem_raw[];
    const uint32_t sb  = smem_u32(smem_raw);
    const int tid  = threadIdx.x;
    const int wid  = tid >> 5;
    const int lane = tid & 31;
    const int n0   = blockIdx.x * 64;
    const int m0   = blockIdx.y * 128;
    const int wm   = wid & 3;       // 4 warps in M (32 rows each)
    const int wn   = wid >> 2;      // 2 warps in N (32 cols each)

    const long batch = bstride ? (long)(m0 >> 10) : 0;
    const __nv_bfloat16* srcA[2] = {Ahi, Alo};
    const __nv_bfloat16* srcB[2] = {Bhi + batch * bstride, Blo + batch * bstride};

    float acc[2][4][4];
#pragma unroll
    for (int i = 0; i < 2; i++)
#pragma unroll
        for (int j = 0; j < 4; j++)
#pragma unroll
            for (int k = 0; k < 4; k++) acc[i][j][k] = 0.f;

    // ldmatrix per-thread offsets within a tile (80B row stride)
    const uint32_t a_roff = (uint32_t)((wm * 32 + (lane & 15)) * 80 + (lane >> 4) * 16);
    const uint32_t b_roff = (uint32_t)((wn * 32 + ((lane >> 4) << 3) + (lane & 7)) * 80
                                       + ((lane >> 3) & 1) * 16);

    const int NC = KDIM / 32;

    // async staging of one K-chunk into buffer `buf`
    auto stage = [&](int kk, uint32_t buf) {
#pragma unroll
        for (int i = 0; i < 4; i++) {          // A tiles: 1024 segs
            int idx  = i * 256 + tid;
            int tile = idx >> 9;
            int row  = (idx >> 2) & 127;
            int seg  = idx & 3;
            cpasync16(buf + tile * 10240 + row * 80 + seg * 16,
                      srcA[tile] + (size_t)(m0 + row) * KDIM + kk + seg * 8);
        }
#pragma unroll
        for (int i = 0; i < 2; i++) {          // B tiles: 512 segs
            int idx  = i * 256 + tid;
            int tile = idx >> 8;
            int row  = (idx >> 2) & 63;
            int seg  = idx & 3;
            cpasync16(buf + 20480 + tile * 5120 + row * 80 + seg * 16,
                      srcB[tile] + (size_t)(n0 + row) * KDIM + kk + seg * 8);
        }
        CP_COMMIT();
    };

    stage(0, sb);

    for (int t = 0; t < NC; t++) {
        CP_WAIT0();
        __syncthreads();

        if (t + 1 < NC) stage((t + 1) * 32, sb + (uint32_t)((t + 1) & 1) * BUF_B);

        const uint32_t base = sb + (uint32_t)(t & 1) * BUF_B;
#pragma unroll
        for (int ks = 0; ks < 2; ks++) {
            const uint32_t koff = ks * 32;
            uint32_t ah[2][4], al[2][4];
#pragma unroll
            for (int tm = 0; tm < 2; tm++) {
                ldsm4(base + a_roff + tm * (16 * 80) + koff, ah[tm]);
                ldsm4(base + 10240 + a_roff + tm * (16 * 80) + koff, al[tm]);
            }
#pragma unroll
            for (int tnp = 0; tnp < 2; tnp++) {
                uint32_t bh[4], bl[4];
                ldsm4(base + 20480 + b_roff + tnp * (16 * 80) + koff, bh);
                ldsm4(base + 25600 + b_roff + tnp * (16 * 80) + koff, bl);
#pragma unroll
                for (int tm = 0; tm < 2; tm++)
#pragma unroll
                    for (int hf = 0; hf < 2; hf++)
                        mma16816(acc[tm][tnp * 2 + hf], ah[tm], bh + hf * 2);
#pragma unroll
                for (int tm = 0; tm < 2; tm++)
#pragma unroll
                    for (int hf = 0; hf < 2; hf++)
                        mma16816(acc[tm][tnp * 2 + hf], ah[tm], bl + hf * 2);
#pragma unroll
                for (int tm = 0; tm < 2; tm++)
#pragma unroll
                    for (int hf = 0; hf < 2; hf++)
                        mma16816(acc[tm][tnp * 2 + hf], al[tm], bh + hf * 2);
            }
        }
    }

    if (EPI == 3) {
#pragma unroll
        for (int tm = 0; tm < 2; tm++)
#pragma unroll
            for (int hf = 0; hf < 2; hf++) {
                const int row = m0 + wm * 32 + tm * 16 + hf * 8 + (lane >> 2);
#pragma unroll
                for (int tn = 0; tn < 4; tn++) {
                    const int col = n0 + wn * 32 + tn * 8 + (lane & 3) * 2;
                    float v0 = acc[tm][tn][hf * 2 + 0];
                    float v1 = acc[tm][tn][hf * 2 + 1];
                    const float* bp = (col < LATD) ? (bias + col) : (bias2 + col - LATD);
                    float2 bv = *(const float2*)bp;
                    v0 += bv.x; v1 += bv.y;
                    float* dst = (col < LATD)
                        ? (outf + (size_t)row * LATD + col)
                        : (outf + (size_t)TOK * LATD + (size_t)row * LATD + (col - LATD));
                    *(float2*)dst = make_float2(v0, v1);
                }
            }
        return;
    }

    // EPI 0/1: epilogue math, SMEM restage, 16B/lane global stores
    __syncthreads();
    char* hi_st = smem_raw;                 // 128 * 144 = 18432
    char* lo_st = smem_raw + 20480;
#pragma unroll
    for (int tm = 0; tm < 2; tm++) {
#pragma unroll
        for (int hf = 0; hf < 2; hf++) {
            const int rl = wm * 32 + tm * 16 + hf * 8 + (lane >> 2);
            const int row = m0 + rl;
            float di = 0.f, d2 = 0.f;
            if (EPI == 0) { di = g_d[row]; d2 = di * di; }
#pragma unroll
            for (int tn = 0; tn < 4; tn++) {
                const int cl = wn * 32 + tn * 8 + (lane & 3) * 2;
                float v0 = acc[tm][tn][hf * 2 + 0];
                float v1 = acc[tm][tn][hf * 2 + 1];
                if (EPI == 0) {
                    float2 xv = *(const float2*)(xdiag + (size_t)row * LDO + n0 + cl);
                    v0 = di * v0 + d2 * xv.x;
                    v1 = di * v1 + d2 * xv.y;
                } else {
                    float2 bv = *(const float2*)(bias + n0 + cl);
                    v0 = fmaxf(v0 + bv.x, 0.f);
                    v1 = fmaxf(v1 + bv.y, 0.f);
                }
                __nv_bfloat16 h0 = __float2bfloat16(v0);
                __nv_bfloat16 h1 = __float2bfloat16(v1);
                *(__nv_bfloat162*)(hi_st + rl * STG_STRIDE + cl * 2) = __nv_bfloat162(h0, h1);
                *(__nv_bfloat162*)(lo_st + rl * STG_STRIDE + cl * 2) = __nv_bfloat162(
                    __float2bfloat16(v0 - __bfloat162float(h0)),
                    __float2bfloat16(v1 - __bfloat162float(h1)));
            }
        }
    }
    __syncthreads();
#pragma unroll
    for (int it = 0; it < 4; it++) {
        int lin = it * 256 + tid;        // 0..1023
        int r   = lin >> 3;              // 0..127
        int c16 = lin & 7;               // 16B segment (64 cols = 8 segs)
        uint4 vh = *(uint4*)(hi_st + r * STG_STRIDE + c16 * 16);
        uint4 vl = *(uint4*)(lo_st + r * STG_STRIDE + c16 * 16);
        size_t go = (size_t)(m0 + r) * LDO + n0 + c16 * 8;
        *(uint4*)(ohi + go) = vh;
        *(uint4*)(olo + go) = vl;
    }
}

// ---------------------------------------------------------------------------
extern "C" void kernel_launch(void* const* d_in, const int* in_sizes, int n_in,
                              void* d_out, int out_size) {
    const float* x   = (const float*)d_in[0];
    const float* a   = (const float*)d_in[1];
    const float* W1  = (const float*)d_in[2];
    const float* b1  = (const float*)d_in[3];
    const float* Wmu = (const float*)d_in[4];
    const float* bmu = (const float*)d_in[5];
    const float* Wlv = (const float*)d_in[6];
    const float* blv = (const float*)d_in[7];
    float* out = (float*)d_out;

    cudaFuncSetAttribute(gemm_k<NNODE, 0, IND>,  cudaFuncAttributeMaxDynamicSharedMemorySize, GEMM_SMEM);
    cudaFuncSetAttribute(gemm_k<IND,   1, HIDD>, cudaFuncAttributeMaxDynamicSharedMemorySize, GEMM_SMEM);
    cudaFuncSetAttribute(gemm_k<HIDD,  3, LATD>, cudaFuncAttributeMaxDynamicSharedMemorySize, GEMM_SMEM);

    __nv_bfloat16 *ahi, *alo, *xthi, *xtlo, *hhi, *hlo, *h1hi, *h1lo;
    __nv_bfloat16 *w1hi, *w1lo, *wchi, *wclo;
    cudaGetSymbolAddress((void**)&ahi,  g_ahi);  cudaGetSymbolAddress((void**)&alo,  g_alo);
    cudaGetSymbolAddress((void**)&xthi, g_xthi); cudaGetSymbolAddress((void**)&xtlo, g_xtlo);
    cudaGetSymbolAddress((void**)&hhi,  g_hhi);  cudaGetSymbolAddress((void**)&hlo,  g_hlo);
    cudaGetSymbolAddress((void**)&h1hi, g_h1hi); cudaGetSymbolAddress((void**)&h1lo, g_h1lo);
    cudaGetSymbolAddress((void**)&w1hi, g_w1hi); cudaGetSymbolAddress((void**)&w1lo, g_w1lo);
    cudaGetSymbolAddress((void**)&wchi, g_wcathi); cudaGetSymbolAddress((void**)&wclo, g_wcatlo);

    // #1 fused adjacency split + degree factors
    dsplit_a_kernel<<<TOK / 8, 256>>>(a);
    // #2 x transpose + d_j scale + split
    split_xt_kernel<<<dim3(IND / 32, NNODE / 32, BB), dim3(32, 8)>>>(x);
    // #3 all weight splits
    split_w_kernel<<<(W1_F4 + 2 * WHD_F4) / 256, 256>>>(W1, Wmu, Wlv);
    // #4 message passing GEMM (profiled launch)
    gemm_k<NNODE, 0, IND><<<dim3(IND / 64, TOK / 128), 256, GEMM_SMEM>>>(
        ahi, alo, xthi, xtlo, (long)IND * NNODE, nullptr, hhi, hlo, nullptr, nullptr, x);
    // #5 h1 = relu(h @ W1^T + b1)
    gemm_k<IND, 1, HIDD><<<dim3(HIDD / 64, TOK / 128), 256, GEMM_SMEM>>>(
        hhi, hlo, w1hi, w1lo, 0, nullptr, h1hi, h1lo, b1, nullptr, nullptr);
    // #6 fused mu+logvar heads: one N=512 GEMM over [Wmu; Wlv]
    gemm_k<HIDD, 3, LATD><<<dim3((2 * LATD) / 64, TOK / 128), 256, GEMM_SMEM>>>(
        h1hi, h1lo, wchi, wclo, 0, out, nullptr, nullptr, bmu, blv, nullptr);
}

// round 8
// speedup vs baseline: 1.6906x; 1.6906x over previous
#include <cuda_runtime.h>
#include <cuda_bf16.h>
#include <cstdint>

#define BB    64
#define NNODE 1024
#define IND   512
#define HIDD  1024
#define LATD  256
#define TOK   (BB * NNODE)   // 65536

// ---------------------------------------------------------------------------
// Scratch (device globals — allocation is forbidden)
// ---------------------------------------------------------------------------
__device__ float g_d[TOK];
__device__ __align__(16) __nv_bfloat16 g_ahi[(size_t)BB * NNODE * NNODE];
__device__ __align__(16) __nv_bfloat16 g_alo[(size_t)BB * NNODE * NNODE];
__device__ __align__(16) __nv_bfloat16 g_xthi[(size_t)BB * IND * NNODE];
__device__ __align__(16) __nv_bfloat16 g_xtlo[(size_t)BB * IND * NNODE];
__device__ __align__(16) __nv_bfloat16 g_hhi[(size_t)TOK * IND];
__device__ __align__(16) __nv_bfloat16 g_hlo[(size_t)TOK * IND];
__device__ __align__(16) __nv_bfloat16 g_h1hi[(size_t)TOK * HIDD];
__device__ __align__(16) __nv_bfloat16 g_h1lo[(size_t)TOK * HIDD];
__device__ __align__(16) __nv_bfloat16 g_w1hi[HIDD * IND],  g_w1lo[HIDD * IND];
__device__ __align__(16) __nv_bfloat16 g_wcathi[2 * LATD * HIDD];   // [Wmu; Wlv]
__device__ __align__(16) __nv_bfloat16 g_wcatlo[2 * LATD * HIDD];

// ---------------------------------------------------------------------------
// helpers (baseline PTX only)
// ---------------------------------------------------------------------------
__device__ __forceinline__ uint32_t smem_u32(const void* p) {
    uint32_t a;
    asm("{ .reg .u64 t; cvta.to.shared.u64 t, %1; cvt.u32.u64 %0, t; }" : "=r"(a) : "l"(p));
    return a;
}
__device__ __forceinline__ void ldsm4(uint32_t addr, uint32_t* r) {
    asm volatile("ldmatrix.sync.aligned.m8n8.x4.shared.b16 {%0,%1,%2,%3}, [%4];"
                 : "=r"(r[0]), "=r"(r[1]), "=r"(r[2]), "=r"(r[3]) : "r"(addr));
}
__device__ __forceinline__ void mma16816(float* c, const uint32_t* a, const uint32_t* b) {
    asm volatile(
        "mma.sync.aligned.m16n8k16.row.col.f32.bf16.bf16.f32 "
        "{%0,%1,%2,%3}, {%4,%5,%6,%7}, {%8,%9}, {%0,%1,%2,%3};"
        : "+f"(c[0]), "+f"(c[1]), "+f"(c[2]), "+f"(c[3])
        : "r"(a[0]), "r"(a[1]), "r"(a[2]), "r"(a[3]), "r"(b[0]), "r"(b[1]));
}
__device__ __forceinline__ void cpasync16(uint32_t dst, const void* src) {
    asm volatile("cp.async.cg.shared.global [%0], [%1], 16;" :: "r"(dst), "l"(src) : "memory");
}
#define CP_COMMIT() asm volatile("cp.async.commit_group;" ::: "memory")
#define CP_WAIT0()  asm volatile("cp.async.wait_group 0;" ::: "memory")
#define CP_WAIT1()  asm volatile("cp.async.wait_group 1;" ::: "memory")

// ---------------------------------------------------------------------------
// Fused: a -> (hi, lo) split AND degree d = rsqrt(rowsum + 1 + 1e-8)
// ---------------------------------------------------------------------------
__global__ void __launch_bounds__(256) dsplit_a_kernel(const float* __restrict__ a) {
    int warp = (blockIdx.x * 256 + threadIdx.x) >> 5;
    int lane = threadIdx.x & 31;
    const float4* row = (const float4*)(a + (size_t)warp * NNODE);
    __nv_bfloat162* hi = (__nv_bfloat162*)(g_ahi + (size_t)warp * NNODE);
    __nv_bfloat162* lo = (__nv_bfloat162*)(g_alo + (size_t)warp * NNODE);
    float s = 0.f;
#pragma unroll
    for (int j = 0; j < 8; j++) {
        int i4 = lane + j * 32;
        float4 v = row[i4];
        s += v.x + v.y + v.z + v.w;
        float f[4] = {v.x, v.y, v.z, v.w};
        __nv_bfloat16 h[4], l[4];
#pragma unroll
        for (int k = 0; k < 4; k++) {
            h[k] = __float2bfloat16(f[k]);
            l[k] = __float2bfloat16(f[k] - __bfloat162float(h[k]));
        }
        hi[2 * i4]     = __nv_bfloat162(h[0], h[1]);
        hi[2 * i4 + 1] = __nv_bfloat162(h[2], h[3]);
        lo[2 * i4]     = __nv_bfloat162(l[0], l[1]);
        lo[2 * i4 + 1] = __nv_bfloat162(l[2], l[3]);
    }
#pragma unroll
    for (int off = 16; off; off >>= 1) s += __shfl_xor_sync(0xffffffffu, s, off);
    if (lane == 0) g_d[warp] = rsqrtf(s + 1.0f + 1e-8f);
}

// ---------------------------------------------------------------------------
// Kernel: xt[b,c,j] = d[b,j] * x[b,j,c]  transposed + split into hi/lo
// ---------------------------------------------------------------------------
__global__ void __launch_bounds__(256) split_xt_kernel(const float* __restrict__ x) {
    __shared__ float t[32][33];
    int b  = blockIdx.z;
    int j0 = blockIdx.y * 32;
    int c0 = blockIdx.x * 32;
    int tx = threadIdx.x, ty = threadIdx.y;      // (32, 8)
#pragma unroll
    for (int k = 0; k < 4; k++) {
        int j = j0 + ty + k * 8;
        float dv = g_d[b * NNODE + j];
        t[ty + k * 8][tx] = x[((size_t)(b * NNODE + j)) * IND + c0 + tx] * dv;
    }
    __syncthreads();
#pragma unroll
    for (int k = 0; k < 4; k++) {
        int c = c0 + ty + k * 8;
        int j = j0 + tx;
        float v = t[tx][ty + k * 8];
        __nv_bfloat16 h = __float2bfloat16(v);
        size_t o = ((size_t)b * IND + c) * NNODE + j;
        g_xthi[o] = h;
        g_xtlo[o] = __float2bfloat16(v - __bfloat162float(h));
    }
}

// ---------------------------------------------------------------------------
// All weight splits in one kernel
// ---------------------------------------------------------------------------
#define W1_F4   (HIDD * IND / 4)          // 131072
#define WHD_F4  (LATD * HIDD / 4)         // 65536
__global__ void __launch_bounds__(256) split_w_kernel(const float* __restrict__ W1,
                                                      const float* __restrict__ Wmu,
                                                      const float* __restrict__ Wlv) {
    size_t i = (size_t)blockIdx.x * 256 + threadIdx.x;
    const float* src; __nv_bfloat16 *hi, *lo; size_t o;
    if (i < W1_F4)                 { src = W1;  hi = g_w1hi;  lo = g_w1lo;  o = i; }
    else if (i < W1_F4 + WHD_F4)   { src = Wmu; hi = g_wcathi; lo = g_wcatlo; o = i - W1_F4; }
    else                           { src = Wlv; hi = g_wcathi + (size_t)LATD * HIDD;
                                     lo = g_wcatlo + (size_t)LATD * HIDD; o = i - W1_F4 - WHD_F4; }
    float4 v = ((const float4*)src)[o];
    float f[4] = {v.x, v.y, v.z, v.w};
    __nv_bfloat16 h[4], l[4];
#pragma unroll
    for (int k = 0; k < 4; k++) {
        h[k] = __float2bfloat16(f[k]);
        l[k] = __float2bfloat16(f[k] - __bfloat162float(h[k]));
    }
    ((__nv_bfloat162*)hi)[2 * o]     = __nv_bfloat162(h[0], h[1]);
    ((__nv_bfloat162*)hi)[2 * o + 1] = __nv_bfloat162(h[2], h[3]);
    ((__nv_bfloat162*)lo)[2 * o]     = __nv_bfloat162(l[0], l[1]);
    ((__nv_bfloat162*)lo)[2 * o + 1] = __nv_bfloat162(l[2], l[3]);
}

// ---------------------------------------------------------------------------
// Split-bf16 GEMM via mma.sync (HMMA): D[m,n] = sum_k A[m,k]*B[n,k]
//   3-term compensation: Ahi*Bhi + Ahi*Blo + Alo*Bhi  (fp32-equivalent)
// CTA tile 128x128 (R6 config, ratio 4), KC=32, **3-stage cp.async pipeline**.
// SMEM tiles: 64B row stride + XOR swizzle seg'=(seg+(row>>1))&3 (conflict-free
// for STS.128 and ldmatrix; swizzle invariant under +16-row steps).
// Buffer = 4 tiles * 128 * 64B = 32 KB; 3 buffers = 96 KB; 2 CTAs/SM.
// EPI: 0 = message passing (hi/lo out), 1 = bias+relu (hi/lo out),
//      3 = dual-head bias (cols<256 -> mu else logvar), fp32 out
// ---------------------------------------------------------------------------
#define TILE_B 8192
#define BUF_B  32768
#define GEMM_SMEM 98304
#define STG_STRIDE 272      // (128+8) bf16 per row (epilogue restage)

template <int KDIM, int EPI, int LDO>
__global__ void __launch_bounds__(256, 2) gemm_k(
    const __nv_bfloat16* __restrict__ Ahi, const __nv_bfloat16* __restrict__ Alo,
    const __nv_bfloat16* __restrict__ Bhi, const __nv_bfloat16* __restrict__ Blo,
    long bstride,
    float* __restrict__ outf,
    __nv_bfloat16* __restrict__ ohi, __nv_bfloat16* __restrict__ olo,
    const float* __restrict__ bias, const float* __restrict__ bias2,
    const float* __restrict__ xdiag)
{
    extern __shared__ char smem_raw[];
    const uint32_t sb  = smem_u32(smem_raw);
    const int tid  = threadIdx.x;
    const int wid  = tid >> 5;
    const int lane = tid & 31;
    const int n0   = blockIdx.x * 128;
    const int m0   = blockIdx.y * 128;
    const int wm   = wid & 3;       // 4 warps in M (32 rows)
    const int wn   = wid >> 2;      // 2 warps in N (64 cols)

    const long batch = bstride ? (long)(m0 >> 10) : 0;
    const __nv_bfloat16* srcA[2] = {Ahi, Alo};
    const __nv_bfloat16* srcB[2] = {Bhi + batch * bstride, Blo + batch * bstride};

    float acc[2][8][4];
#pragma unroll
    for (int i = 0; i < 2; i++)
#pragma unroll
        for (int j = 0; j < 8; j++)
#pragma unroll
            for (int k = 0; k < 4; k++) acc[i][j][k] = 0.f;

    // staging: idx -> tile(row,seg); swizzled 16B segment within 64B row
    const int srow = (tid >> 2) & 127;       // helper defaults; real mapping in stage()
    (void)srow;

    // ldmatrix per-lane constants (swizzle folded per lane)
    const int a_row  = wm * 32 + (lane & 15);
    const int a_sw0  = ((lane >> 4) + (a_row >> 1)) & 3;     // seg at ks=0
    const uint32_t a_base = (uint32_t)(a_row * 64);
    const int b_row  = wn * 64 + ((lane >> 4) << 3) + (lane & 7);
    const int b_sw0  = (((lane >> 3) & 1) + (b_row >> 1)) & 3;
    const uint32_t b_base = (uint32_t)(b_row * 64);

    const int NC = KDIM / 32;

    auto stage = [&](int kk, uint32_t buf) {
        // A tiles (hi,lo): 2 * 128 rows * 4 segs = 1024
#pragma unroll
        for (int i = 0; i < 4; i++) {
            int idx  = i * 256 + tid;
            int tile = idx >> 9;
            int row  = (idx >> 2) & 127;
            int seg  = idx & 3;
            uint32_t sw = (uint32_t)(((seg + (row >> 1)) & 3) << 4);
            cpasync16(buf + tile * TILE_B + row * 64 + sw,
                      srcA[tile] + (size_t)(m0 + row) * KDIM + kk + seg * 8);
        }
        // B tiles (hi,lo): 2 * 128 rows * 4 segs = 1024
#pragma unroll
        for (int i = 0; i < 4; i++) {
            int idx  = i * 256 + tid;
            int tile = idx >> 9;
            int row  = (idx >> 2) & 127;
            int seg  = idx & 3;
            uint32_t sw = (uint32_t)(((seg + (row >> 1)) & 3) << 4);
            cpasync16(buf + 2 * TILE_B + tile * TILE_B + row * 64 + sw,
                      srcB[tile] + (size_t)(n0 + row) * KDIM + kk + seg * 8);
        }
        CP_COMMIT();
    };

    // prologue: two chunks in flight
    stage(0, sb);
    if (NC > 1) stage(32, sb + BUF_B);

    int bufidx = 0;
    for (int t = 0; t < NC; t++) {
        if (t == NC - 1) { CP_WAIT0(); } else { CP_WAIT1(); }
        __syncthreads();

        if (t + 2 < NC) {
            int nb = bufidx + 2; if (nb >= 3) nb -= 3;
            stage((t + 2) * 32, sb + (uint32_t)nb * BUF_B);
        }

        const uint32_t base = sb + (uint32_t)bufidx * BUF_B;
        if (++bufidx == 3) bufidx = 0;

#pragma unroll
        for (int ks = 0; ks < 2; ks++) {
            const uint32_t aswk = (uint32_t)(((a_sw0 + ks * 2) & 3) << 4);
            const uint32_t bswk = (uint32_t)(((b_sw0 + ks * 2) & 3) << 4);
            uint32_t ah[2][4], al[2][4];
#pragma unroll
            for (int tm = 0; tm < 2; tm++) {
                ldsm4(base + a_base + tm * 1024 + aswk, ah[tm]);
                ldsm4(base + TILE_B + a_base + tm * 1024 + aswk, al[tm]);
            }
#pragma unroll
            for (int tnp = 0; tnp < 4; tnp++) {
                uint32_t bh[4], bl[4];
                ldsm4(base + 2 * TILE_B + b_base + tnp * 1024 + bswk, bh);
                ldsm4(base + 3 * TILE_B + b_base + tnp * 1024 + bswk, bl);
#pragma unroll
                for (int tm = 0; tm < 2; tm++)
#pragma unroll
                    for (int hf = 0; hf < 2; hf++)
                        mma16816(acc[tm][tnp * 2 + hf], ah[tm], bh + hf * 2);
#pragma unroll
                for (int tm = 0; tm < 2; tm++)
#pragma unroll
                    for (int hf = 0; hf < 2; hf++)
                        mma16816(acc[tm][tnp * 2 + hf], ah[tm], bl + hf * 2);
#pragma unroll
                for (int tm = 0; tm < 2; tm++)
#pragma unroll
                    for (int hf = 0; hf < 2; hf++)
                        mma16816(acc[tm][tnp * 2 + hf], al[tm], bh + hf * 2);
            }
        }
    }

    if (EPI == 3) {
#pragma unroll
        for (int tm = 0; tm < 2; tm++)
#pragma unroll
            for (int hf = 0; hf < 2; hf++) {
                const int row = m0 + wm * 32 + tm * 16 + hf * 8 + (lane >> 2);
#pragma unroll
                for (int tn = 0; tn < 8; tn++) {
                    const int col = n0 + wn * 64 + tn * 8 + (lane & 3) * 2;
                    float v0 = acc[tm][tn][hf * 2 + 0];
                    float v1 = acc[tm][tn][hf * 2 + 1];
                    const float* bp = (col < LATD) ? (bias + col) : (bias2 + col - LATD);
                    float2 bv = *(const float2*)bp;
                    v0 += bv.x; v1 += bv.y;
                    float* dst = (col < LATD)
                        ? (outf + (size_t)row * LATD + col)
                        : (outf + (size_t)TOK * LATD + (size_t)row * LATD + (col - LATD));
                    *(float2*)dst = make_float2(v0, v1);
                }
            }
        return;
    }

    // EPI 0/1: epilogue math, SMEM restage, 16B/lane global stores
    __syncthreads();
    char* hi_st = smem_raw;                 // 128 * 272 = 34816
    char* lo_st = smem_raw + 49152;
#pragma unroll
    for (int tm = 0; tm < 2; tm++) {
#pragma unroll
        for (int hf = 0; hf < 2; hf++) {
            const int rl = wm * 32 + tm * 16 + hf * 8 + (lane >> 2);
            const int row = m0 + rl;
            float di = 0.f, d2 = 0.f;
            if (EPI == 0) { di = g_d[row]; d2 = di * di; }
#pragma unroll
            for (int tn = 0; tn < 8; tn++) {
                const int cl = wn * 64 + tn * 8 + (lane & 3) * 2;
                float v0 = acc[tm][tn][hf * 2 + 0];
                float v1 = acc[tm][tn][hf * 2 + 1];
                if (EPI == 0) {
                    float2 xv = *(const float2*)(xdiag + (size_t)row * LDO + n0 + cl);
                    v0 = di * v0 + d2 * xv.x;
                    v1 = di * v1 + d2 * xv.y;
                } else {
                    float2 bv = *(const float2*)(bias + n0 + cl);
                    v0 = fmaxf(v0 + bv.x, 0.f);
                    v1 = fmaxf(v1 + bv.y, 0.f);
                }
                __nv_bfloat16 h0 = __float2bfloat16(v0);
                __nv_bfloat16 h1 = __float2bfloat16(v1);
                *(__nv_bfloat162*)(hi_st + rl * STG_STRIDE + cl * 2) = __nv_bfloat162(h0, h1);
                *(__nv_bfloat162*)(lo_st + rl * STG_STRIDE + cl * 2) = __nv_bfloat162(
                    __float2bfloat16(v0 - __bfloat162float(h0)),
                    __float2bfloat16(v1 - __bfloat162float(h1)));
            }
        }
    }
    __syncthreads();
#pragma unroll
    for (int it = 0; it < 8; it++) {
        int lin = it * 256 + tid;
        int r   = lin >> 4;
        int c16 = lin & 15;
        uint4 vh = *(uint4*)(hi_st + r * STG_STRIDE + c16 * 16);
        uint4 vl = *(uint4*)(lo_st + r * STG_STRIDE + c16 * 16);
        size_t go = (size_t)(m0 + r) * LDO + n0 + c16 * 8;
        *(uint4*)(ohi + go) = vh;
        *(uint4*)(olo + go) = vl;
    }
}

// ---------------------------------------------------------------------------
extern "C" void kernel_launch(void* const* d_in, const int* in_sizes, int n_in,
                              void* d_out, int out_size) {
    const float* x   = (const float*)d_in[0];
    const float* a   = (const float*)d_in[1];
    const float* W1  = (const float*)d_in[2];
    const float* b1  = (const float*)d_in[3];
    const float* Wmu = (const float*)d_in[4];
    const float* bmu = (const float*)d_in[5];
    const float* Wlv = (const float*)d_in[6];
    const float* blv = (const float*)d_in[7];
    float* out = (float*)d_out;

    cudaFuncSetAttribute(gemm_k<NNODE, 0, IND>,  cudaFuncAttributeMaxDynamicSharedMemorySize, GEMM_SMEM);
    cudaFuncSetAttribute(gemm_k<IND,   1, HIDD>, cudaFuncAttributeMaxDynamicSharedMemorySize, GEMM_SMEM);
    cudaFuncSetAttribute(gemm_k<HIDD,  3, LATD>, cudaFuncAttributeMaxDynamicSharedMemorySize, GEMM_SMEM);

    __nv_bfloat16 *ahi, *alo, *xthi, *xtlo, *hhi, *hlo, *h1hi, *h1lo;
    __nv_bfloat16 *w1hi, *w1lo, *wchi, *wclo;
    cudaGetSymbolAddress((void**)&ahi,  g_ahi);  cudaGetSymbolAddress((void**)&alo,  g_alo);
    cudaGetSymbolAddress((void**)&xthi, g_xthi); cudaGetSymbolAddress((void**)&xtlo, g_xtlo);
    cudaGetSymbolAddress((void**)&hhi,  g_hhi);  cudaGetSymbolAddress((void**)&hlo,  g_hlo);
    cudaGetSymbolAddress((void**)&h1hi, g_h1hi); cudaGetSymbolAddress((void**)&h1lo, g_h1lo);
    cudaGetSymbolAddress((void**)&w1hi, g_w1hi); cudaGetSymbolAddress((void**)&w1lo, g_w1lo);
    cudaGetSymbolAddress((void**)&wchi, g_wcathi); cudaGetSymbolAddress((void**)&wclo, g_wcatlo);

    // #1 fused adjacency split + degree factors
    dsplit_a_kernel<<<TOK / 8, 256>>>(a);
    // #2 x transpose + d_j scale + split
    split_xt_kernel<<<dim3(IND / 32, NNODE / 32, BB), dim3(32, 8)>>>(x);
    // #3 all weight splits
    split_w_kernel<<<(W1_F4 + 2 * WHD_F4) / 256, 256>>>(W1, Wmu, Wlv);
    // #4 message passing GEMM (profiled launch)
    gemm_k<NNODE, 0, IND><<<dim3(IND / 128, TOK / 128), 256, GEMM_SMEM>>>(
        ahi, alo, xthi, xtlo, (long)IND * NNODE, nullptr, hhi, hlo, nullptr, nullptr, x);
    // #5 h1 = relu(h @ W1^T + b1)
    gemm_k<IND, 1, HIDD><<<dim3(HIDD / 128, TOK / 128), 256, GEMM_SMEM>>>(
        hhi, hlo, w1hi, w1lo, 0, nullptr, h1hi, h1lo, b1, nullptr, nullptr);
    // #6 fused mu+logvar heads: one N=512 GEMM over [Wmu; Wlv]
    gemm_k<HIDD, 3, LATD><<<dim3((2 * LATD) / 128, TOK / 128), 256, GEMM_SMEM>>>(
        h1hi, h1lo, wchi, wclo, 0, out, nullptr, nullptr, bmu, blv, nullptr);
}